// round 13
// baseline (speedup 1.0000x reference)
#include <cuda_runtime.h>
#include <cuda_fp16.h>
#include <cstdint>
#include <cstddef>
#include <math.h>

#define N_FFT   16000
#define BATCH   512
#define D_IN    2048
#define ODIM    3000
#define OPAD    3072
#define KDIM    16000

// Scratch (device globals — allocation-free per harness rules)
__device__ float2 g_TW[N_FFT];                         // twiddles
__device__ __align__(16) __half g_Zh[BATCH * KDIM];    // 16 MB (z in fp16)
__device__ __align__(16) __half g_Wh[OPAD * KDIM];     // 96 MB (W in fp16)

static __device__ __forceinline__ float2 cmulf(float2 a, float2 b) {
    return make_float2(a.x * b.x - a.y * b.y, a.x * b.y + a.y * b.x);
}
static __device__ __forceinline__ unsigned smem_u32(const void* p) {
    unsigned a;
    asm("{ .reg .u64 t; cvta.to.shared.u64 t, %1; cvt.u32.u64 %0, t; }" : "=r"(a) : "l"(p));
    return a;
}
static __device__ __forceinline__ unsigned swz128(unsigned off) {
    return off ^ ((off >> 3) & 0x70);
}
#define CP_ASYNC16(dst, src) \
    asm volatile("cp.async.cg.shared.global [%0], [%1], 16;" :: "r"(dst), "l"(src))
#define CP_COMMIT() asm volatile("cp.async.commit_group;" ::: "memory")
#define CP_WAIT2()  asm volatile("cp.async.wait_group 2;" ::: "memory")

static __device__ __forceinline__ void ldsm_x4(unsigned addr, unsigned* r) {
    asm volatile("ldmatrix.sync.aligned.m8n8.x4.shared.b16 {%0,%1,%2,%3}, [%4];"
                 : "=r"(r[0]), "=r"(r[1]), "=r"(r[2]), "=r"(r[3]) : "r"(addr));
}
static __device__ __forceinline__ void mma_f16(float* c, const unsigned* a, const unsigned* b) {
    asm volatile(
        "mma.sync.aligned.m16n8k16.row.col.f32.f16.f16.f32 "
        "{%0,%1,%2,%3}, {%4,%5,%6,%7}, {%8,%9}, {%0,%1,%2,%3};"
        : "+f"(c[0]), "+f"(c[1]), "+f"(c[2]), "+f"(c[3])
        : "r"(a[0]), "r"(a[1]), "r"(a[2]), "r"(a[3]), "r"(b[0]), "r"(b[1]));
}

// ---------------------------------------------------------------------------
__global__ void tw_init_kernel() {
    int j = blockIdx.x * blockDim.x + threadIdx.x;
    if (j < N_FFT) {
        double ang = -2.0 * 3.14159265358979323846 * (double)j / (double)N_FFT;
        double s, c;
        sincos(ang, &s, &c);
        g_TW[j] = make_float2((float)c, (float)s);
    }
}

// ---------------------------------------------------------------------------
// W -> fp16 plane (rows >= ODIM zero-filled). One thread = 8 elements.
// ---------------------------------------------------------------------------
__global__ __launch_bounds__(256) void wconv_kernel(const float* __restrict__ Wm) {
    const int SEG = KDIM / 8;                 // 2000
    int lin = blockIdx.x * blockDim.x + threadIdx.x;
    if (lin >= OPAD * SEG) return;
    int r = lin / SEG;
    int s = lin - r * SEG;
    __half2 h[4];
    if (r < ODIM) {
        const float4* p = reinterpret_cast<const float4*>(Wm + (size_t)r * KDIM + s * 8);
        float4 a = p[0], b = p[1];
        h[0] = __floats2half2_rn(a.x, a.y);
        h[1] = __floats2half2_rn(a.z, a.w);
        h[2] = __floats2half2_rn(b.x, b.y);
        h[3] = __floats2half2_rn(b.z, b.w);
    } else {
        h[0] = h[1] = h[2] = h[3] = __floats2half2_rn(0.f, 0.f);
    }
    *reinterpret_cast<uint4*>(g_Wh + (size_t)r * KDIM + s * 8) =
        *reinterpret_cast<uint4*>(h);
}

// ---------------------------------------------------------------------------
// FFT core: Step A (radix-4 x2 + radix-8) + Step C (radix-5 x3, stage 0 folds
// the inter-step twiddle). After core: slot s = q*125 + j holds spectrum index
// k = k1(q) + 128*k2(j), k1(q) = (q>>5)+((q>>3)&3)*4+(q&7)*16, k2(j) = rev5(j).
// ---------------------------------------------------------------------------
template <bool INV>
static __device__ __forceinline__ void fft_core(float2* A, const float2* W125,
                                                int tid, int T) {
    // ---- Step A: radix-4 x2 ----
    {
        const int subs4[2] = {32, 8};
        const int twm[2]   = {125, 500};
#pragma unroll
        for (int s = 0; s < 2; ++s) {
            const int sub = subs4[s];
            const int L = 4 * sub;
            const int tm = twm[s];
            for (int i = tid; i < 4000; i += T) {
                int n2 = i % 125;
                int t  = i / 125;               // 0..31
                int blk = t / sub;
                int j   = t - blk * sub;
                int base = (blk * L + j) * 125 + n2;
                const int st = sub * 125;
                float2 x0v = A[base];
                float2 x1v = A[base + st];
                float2 x2v = A[base + 2 * st];
                float2 x3v = A[base + 3 * st];
                float2 t0 = make_float2(x0v.x + x2v.x, x0v.y + x2v.y);
                float2 t1 = make_float2(x0v.x - x2v.x, x0v.y - x2v.y);
                float2 t2 = make_float2(x1v.x + x3v.x, x1v.y + x3v.y);
                float2 t3 = make_float2(x1v.x - x3v.x, x1v.y - x3v.y);
                float2 it3 = INV ? make_float2(-t3.y, t3.x) : make_float2(t3.y, -t3.x);
                float2 y0 = make_float2(t0.x + t2.x, t0.y + t2.y);
                float2 y2 = make_float2(t0.x - t2.x, t0.y - t2.y);
                float2 y1 = make_float2(t1.x + it3.x, t1.y + it3.y);
                float2 y3 = make_float2(t1.x - it3.x, t1.y - it3.y);
                float2 w1 = g_TW[j * tm];
                float2 w2 = g_TW[2 * j * tm];
                float2 w3 = g_TW[3 * j * tm];
                if (INV) { w1.y = -w1.y; w2.y = -w2.y; w3.y = -w3.y; }
                A[base]          = y0;
                A[base + st]     = cmulf(y1, w1);
                A[base + 2 * st] = cmulf(y2, w2);
                A[base + 3 * st] = cmulf(y3, w3);
            }
            __syncthreads();
        }
    }
    // ---- Step A final: radix-8 (direct 8-pt DFT, no post-twiddles) ----
    {
        const float h8 = 0.70710678118654752440f;
        for (int i = tid; i < 2000; i += T) {
            int n2 = i % 125;
            int m  = i / 125;                  // 0..15
            int base = m * 1000 + n2;
            float2 x[8];
#pragma unroll
            for (int e = 0; e < 8; ++e) x[e] = A[base + e * 125];
            float2 s0 = make_float2(x[0].x + x[4].x, x[0].y + x[4].y);
            float2 s1 = make_float2(x[0].x - x[4].x, x[0].y - x[4].y);
            float2 s2 = make_float2(x[2].x + x[6].x, x[2].y + x[6].y);
            float2 s3 = make_float2(x[2].x - x[6].x, x[2].y - x[6].y);
            float2 E0 = make_float2(s0.x + s2.x, s0.y + s2.y);
            float2 E2 = make_float2(s0.x - s2.x, s0.y - s2.y);
            float2 E1 = INV ? make_float2(s1.x - s3.y, s1.y + s3.x)
                            : make_float2(s1.x + s3.y, s1.y - s3.x);
            float2 E3 = INV ? make_float2(s1.x + s3.y, s1.y - s3.x)
                            : make_float2(s1.x - s3.y, s1.y + s3.x);
            float2 t0 = make_float2(x[1].x + x[5].x, x[1].y + x[5].y);
            float2 t1 = make_float2(x[1].x - x[5].x, x[1].y - x[5].y);
            float2 t2 = make_float2(x[3].x + x[7].x, x[3].y + x[7].y);
            float2 t3 = make_float2(x[3].x - x[7].x, x[3].y - x[7].y);
            float2 O0 = make_float2(t0.x + t2.x, t0.y + t2.y);
            float2 O2 = make_float2(t0.x - t2.x, t0.y - t2.y);
            float2 O1 = INV ? make_float2(t1.x - t3.y, t1.y + t3.x)
                            : make_float2(t1.x + t3.y, t1.y - t3.x);
            float2 O3 = INV ? make_float2(t1.x + t3.y, t1.y - t3.x)
                            : make_float2(t1.x - t3.y, t1.y + t3.x);
            float2 W1O, W2O, W3O;
            if (!INV) {
                W1O = make_float2(h8 * (O1.x + O1.y), h8 * (O1.y - O1.x));
                W2O = make_float2(O2.y, -O2.x);
                W3O = make_float2(-h8 * (O3.x - O3.y), -h8 * (O3.x + O3.y));
            } else {
                W1O = make_float2(h8 * (O1.x - O1.y), h8 * (O1.y + O1.x));
                W2O = make_float2(-O2.y, O2.x);
                W3O = make_float2(-h8 * (O3.x + O3.y), -h8 * (O3.y - O3.x));
            }
            A[base]           = make_float2(E0.x + O0.x, E0.y + O0.y);
            A[base + 125]     = make_float2(E1.x + W1O.x, E1.y + W1O.y);
            A[base + 250]     = make_float2(E2.x + W2O.x, E2.y + W2O.y);
            A[base + 375]     = make_float2(E3.x + W3O.x, E3.y + W3O.y);
            A[base + 500]     = make_float2(E0.x - O0.x, E0.y - O0.y);
            A[base + 625]     = make_float2(E1.x - W1O.x, E1.y - W1O.y);
            A[base + 750]     = make_float2(E2.x - W2O.x, E2.y - W2O.y);
            A[base + 875]     = make_float2(E3.x - W3O.x, E3.y - W3O.y);
        }
        __syncthreads();
    }
    // ---- Step C: 3 radix-5 DIF stages; stage 0 folds inter-step twiddle ----
    {
        const float c1 = 0.309016994374947424f;
        const float c2 = -0.809016994374947424f;
        const float S1 = INV ? -0.951056516295153572f : 0.951056516295153572f;
        const float S2 = INV ? -0.587785252292473129f : 0.587785252292473129f;
        const int Ls[3]   = {125, 25, 5};
        const int subs[3] = {25, 5, 1};
        const int fs[3]   = {1, 5, 25};
#pragma unroll
        for (int s = 0; s < 3; ++s) {
            const int L = Ls[s], sub = subs[s], f = fs[s];
            for (int i = tid; i < 3200; i += T) {
                int q = i / 25;
                int t = i - q * 25;
                int blk = t / sub;
                int j   = t - blk * sub;
                int base = q * 125 + blk * L + j;
                float2 x0v = A[base];
                float2 x1v = A[base + sub];
                float2 x2v = A[base + 2 * sub];
                float2 x3v = A[base + 3 * sub];
                float2 x4v = A[base + 4 * sub];
                if (s == 0) {
                    int k1 = (q >> 5) + ((q >> 3) & 3) * 4 + (q & 7) * 16;
                    float2 b0 = g_TW[j * k1];
                    float2 b1 = g_TW[(j + 25) * k1];
                    float2 b2 = g_TW[(j + 50) * k1];
                    float2 b3 = g_TW[(j + 75) * k1];
                    float2 b4 = g_TW[(j + 100) * k1];
                    if (INV) { b0.y = -b0.y; b1.y = -b1.y; b2.y = -b2.y; b3.y = -b3.y; b4.y = -b4.y; }
                    x0v = cmulf(x0v, b0);
                    x1v = cmulf(x1v, b1);
                    x2v = cmulf(x2v, b2);
                    x3v = cmulf(x3v, b3);
                    x4v = cmulf(x4v, b4);
                }
                float t1x = x1v.x + x4v.x, t1y = x1v.y + x4v.y;
                float t2x = x2v.x + x3v.x, t2y = x2v.y + x3v.y;
                float t3x = x1v.x - x4v.x, t3y = x1v.y - x4v.y;
                float t4x = x2v.x - x3v.x, t4y = x2v.y - x3v.y;
                float2 y0 = make_float2(x0v.x + t1x + t2x, x0v.y + t1y + t2y);
                float ax = x0v.x + c1 * t1x + c2 * t2x;
                float ay = x0v.y + c1 * t1y + c2 * t2y;
                float bx = S1 * t3x + S2 * t4x;
                float by = S1 * t3y + S2 * t4y;
                float dx = x0v.x + c2 * t1x + c1 * t2x;
                float dy = x0v.y + c2 * t1y + c1 * t2y;
                float ex = S2 * t3x - S1 * t4x;
                float ey = S2 * t3y - S1 * t4y;
                float2 y1 = make_float2(ax + by, ay - bx);
                float2 y4 = make_float2(ax - by, ay + bx);
                float2 y2 = make_float2(dx + ey, dy - ex);
                float2 y3 = make_float2(dx - ey, dy + ex);
                int jf = j * f;
                float2 w1 = W125[jf],  w2 = W125[2 * jf], w3 = W125[3 * jf], w4 = W125[4 * jf];
                if (INV) { w1.y = -w1.y; w2.y = -w2.y; w3.y = -w3.y; w4.y = -w4.y; }
                A[base]           = y0;
                A[base + sub]     = cmulf(y1, w1);
                A[base + 2 * sub] = cmulf(y2, w2);
                A[base + 3 * sub] = cmulf(y3, w3);
                A[base + 4 * sub] = cmulf(y4, w4);
            }
            __syncthreads();
        }
    }
}

// slot of spectrum index k in post-core layout
static __device__ __forceinline__ int slot_of(int k) {
    int k1 = k & 127;
    int k2 = k >> 7;
    int q = (k1 & 3) * 32 + ((k1 >> 2) & 3) * 8 + (k1 >> 4);
    int j = (k2 / 25) + ((k2 / 5) % 5) * 5 + (k2 % 5) * 25;
    return q * 125 + j;
}

// ---------------------------------------------------------------------------
// Fully fused: sketch build -> fwd FFT -> pointwise (conj symmetry) ->
// inverse FFT -> fp16 z store. One CTA (1024 thr) per batch row.
// ---------------------------------------------------------------------------
__global__ __launch_bounds__(1024) void fused_fft_kernel(
    const float* __restrict__ x0, const float* __restrict__ x1,
    const float* __restrict__ s1, const float* __restrict__ s2,
    const int* __restrict__ h1, const int* __restrict__ h2) {
    extern __shared__ float2 sm[];
    float2* A    = sm;            // 16000
    float2* W125 = sm + N_FFT;    // 125

    const int b   = blockIdx.x;
    const int tid = threadIdx.x;
    const int T   = blockDim.x;   // 1024

    for (int k = tid; k < N_FFT; k += T) A[k] = make_float2(0.f, 0.f);
    for (int m = tid; m < 125; m += T) W125[m] = g_TW[128 * m];
    __syncthreads();
    for (int a = tid; a < D_IN; a += T) {
        float v1 = s1[a] * x0[b * D_IN + a];
        float v2 = s2[a] * x1[b * D_IN + a];
        atomicAdd(&A[h1[a]].x, v1);
        atomicAdd(&A[h2[a]].y, v2);
    }
    __syncthreads();

    fft_core<false>(A, W125, tid, T);

    // pointwise: Z[k] = F1[k]*F2[k]; Z[N-k] = conj(Z[k])
    {
        float2 Zreg[8];
#pragma unroll
        for (int it = 0; it < 8; ++it) {
            int k = tid + it * T;
            if (k <= 8000) {
                int sA = slot_of(k);
                int kn = (k == 0) ? 0 : N_FFT - k;
                int sB = (kn == k) ? sA : slot_of(kn);
                float2 C = A[sA], D = A[sB];
                float2 F1 = make_float2(0.5f * (C.x + D.x), 0.5f * (C.y - D.y));
                float2 F2 = make_float2(0.5f * (C.y + D.y), 0.5f * (D.x - C.x));
                Zreg[it] = cmulf(F1, F2);
            }
        }
        __syncthreads();
#pragma unroll
        for (int it = 0; it < 8; ++it) {
            int k = tid + it * T;
            if (k <= 8000) {
                float2 Z = Zreg[it];
                A[k] = Z;
                if (k > 0 && k < 8000)
                    A[N_FFT - k] = make_float2(Z.x, -Z.y);
            }
        }
        __syncthreads();
    }

    fft_core<true>(A, W125, tid, T);

    const float invN = 1.0f / (float)N_FFT;
    for (int k = tid; k < N_FFT; k += T) {
        float2 v = A[slot_of(k)];
        g_Zh[(size_t)b * KDIM + k] = __float2half_rn(v.x * invN);
    }
}

// ---------------------------------------------------------------------------
// fp16 single-term HMMA GEMM:  out = relu(zh @ wh^T + b)
// Tile 128x96, k-chunk 64, grid (32,4)=128 CTAs, 512 thr (16 warps, 4/SMSP),
// warp layout 8m x 2n (warp tile 16x48), 4-stage cp.async pipeline.
// ---------------------------------------------------------------------------
#define GTK 64
#define GITERS (KDIM / GTK)          // 250
#define A_PL 16384
#define B_PL 12288
#define STG_BYTES (A_PL + B_PL)      // 28672
#define NST 4
#define GEMM_SMEM (NST * STG_BYTES)  // 114688
#define GT 512

static __device__ __forceinline__ void gemm_issue_stage(unsigned sb, int tid, int k0,
                                                        int m0, int n0g) {
    const char* zh = reinterpret_cast<const char*>(g_Zh);
    const char* wh = reinterpret_cast<const char*>(g_Wh);
#pragma unroll
    for (int i = 0; i < 2; ++i) {                 // A: 128 rows x 8 segs = 1024
        int lin = i * GT + tid;
        int r = lin >> 3, seg = lin & 7;
        unsigned d = sb + swz128((unsigned)(r * 128 + seg * 16));
        size_t so = ((size_t)(m0 + r) * KDIM + k0 + seg * 8) * 2;
        CP_ASYNC16(d, zh + so);
    }
#pragma unroll
    for (int i = 0; i < 2; ++i) {                 // B: 96 rows x 8 segs = 768
        int lin = i * GT + tid;
        if (lin < 768) {
            int r = lin >> 3, seg = lin & 7;
            unsigned d = sb + A_PL + swz128((unsigned)(r * 128 + seg * 16));
            size_t so = ((size_t)(n0g + r) * KDIM + k0 + seg * 8) * 2;
            CP_ASYNC16(d, wh + so);
        }
    }
}

__global__ __launch_bounds__(GT, 1) void gemm_hmma_kernel(const float* __restrict__ bias,
                                                          float* __restrict__ out) {
    extern __shared__ char gsm[];
    const unsigned sbase = smem_u32(gsm);
    const int tid  = threadIdx.x;
    const int lane = tid & 31;
    const int wid  = tid >> 5;          // 0..15
    const int wm   = wid >> 1;          // 0..7 -> 16 m rows each
    const int wn   = wid & 1;           // 0..1 -> 48 n cols each
    const int n0 = blockIdx.x * 96;
    const int m0 = blockIdx.y * 128;

    float acc[6][4];
#pragma unroll
    for (int j = 0; j < 6; ++j)
#pragma unroll
        for (int e = 0; e < 4; ++e) acc[j][e] = 0.f;

    gemm_issue_stage(sbase, tid, 0, m0, n0);
    CP_COMMIT();
    gemm_issue_stage(sbase + STG_BYTES, tid, GTK, m0, n0);
    CP_COMMIT();
    gemm_issue_stage(sbase + 2 * STG_BYTES, tid, 2 * GTK, m0, n0);
    CP_COMMIT();

    const unsigned aRowSel = (unsigned)(lane & 15) * 128 + ((unsigned)(lane >> 4) << 4);
    const unsigned bRowSel = (unsigned)((lane & 7) | (((lane >> 4) & 1) << 3)) * 128 +
                             (((unsigned)(lane >> 3) & 1) << 4);

    for (int c = 0; c < GITERS; ++c) {
        CP_WAIT2();
        __syncthreads();
        if (c + 3 < GITERS) {
            gemm_issue_stage(sbase + ((c + 3) & 3) * STG_BYTES, tid, (c + 3) * GTK, m0, n0);
        }
        CP_COMMIT();

        const unsigned Ab = sbase + (c & 3) * STG_BYTES;
        const unsigned Bb = Ab + A_PL;
#pragma unroll
        for (int ks = 0; ks < 4; ++ks) {          // 4 sub-chunks of k=16
            unsigned Af[4];
            unsigned Bf[3][4];
            {
                unsigned off = (unsigned)((wm * 16) * 128 + ks * 32) + aRowSel;
                ldsm_x4(Ab + swz128(off), Af);
            }
#pragma unroll
            for (int g = 0; g < 3; ++g) {
                unsigned off = (unsigned)((wn * 48 + g * 16) * 128 + ks * 32) + bRowSel;
                ldsm_x4(Bb + swz128(off), Bf[g]);
            }
#pragma unroll
            for (int nf = 0; nf < 6; ++nf)
                mma_f16(acc[nf], Af, &Bf[nf >> 1][(nf & 1) * 2]);
        }
        __syncthreads();
    }

    // ---- epilogue: bias + relu ----
    {
        int mlo = m0 + wm * 16 + (lane >> 2);
#pragma unroll
        for (int nf = 0; nf < 6; ++nf) {
            int n = n0 + wn * 48 + nf * 8 + 2 * (lane & 3);
            if (n < ODIM) {
                float b0 = bias[n], b1 = bias[n + 1];
                float2 v0, v1;
                v0.x = fmaxf(acc[nf][0] + b0, 0.f);
                v0.y = fmaxf(acc[nf][1] + b1, 0.f);
                v1.x = fmaxf(acc[nf][2] + b0, 0.f);
                v1.y = fmaxf(acc[nf][3] + b1, 0.f);
                *reinterpret_cast<float2*>(out + (size_t)mlo * ODIM + n) = v0;
                *reinterpret_cast<float2*>(out + (size_t)(mlo + 8) * ODIM + n) = v1;
            }
        }
    }
}

// ---------------------------------------------------------------------------
extern "C" void kernel_launch(void* const* d_in, const int* in_sizes, int n_in,
                              void* d_out, int out_size) {
    const float* x0  = (const float*)d_in[0];
    const float* x1  = (const float*)d_in[1];
    const float* s1  = (const float*)d_in[2];
    const float* s2  = (const float*)d_in[3];
    const float* Wm  = (const float*)d_in[4];
    const float* bia = (const float*)d_in[5];
    const int*   h1  = (const int*)d_in[6];
    const int*   h2  = (const int*)d_in[7];
    float* out = (float*)d_out;

    // side stream + events for wconv overlap (created on first, uncaptured call)
    static cudaStream_t side = nullptr;
    static cudaEvent_t evFork = nullptr, evJoin = nullptr;
    if (!side) {
        cudaStreamCreateWithFlags(&side, cudaStreamNonBlocking);
        cudaEventCreateWithFlags(&evFork, cudaEventDisableTiming);
        cudaEventCreateWithFlags(&evJoin, cudaEventDisableTiming);
    }

    const int FFT_SMEM = (N_FFT + 128) * (int)sizeof(float2);  // 129 KB
    cudaFuncSetAttribute(fused_fft_kernel, cudaFuncAttributeMaxDynamicSharedMemorySize, FFT_SMEM);
    cudaFuncSetAttribute(gemm_hmma_kernel, cudaFuncAttributeMaxDynamicSharedMemorySize, GEMM_SMEM);

    // fork: wconv on side stream (DRAM-bound; overlaps compute-bound FFT)
    cudaEventRecord(evFork, 0);
    cudaStreamWaitEvent(side, evFork, 0);
    const int wthreads = OPAD * (KDIM / 8);
    wconv_kernel<<<(wthreads + 255) / 256, 256, 0, side>>>(Wm);
    cudaEventRecord(evJoin, side);

    tw_init_kernel<<<(N_FFT + 255) / 256, 256>>>();

    fused_fft_kernel<<<BATCH, 1024, FFT_SMEM>>>(x0, x1, s1, s2, h1, h2);

    // join: gemm needs g_Wh
    cudaStreamWaitEvent(0, evJoin, 0);
    gemm_hmma_kernel<<<dim3((ODIM + 95) / 96, BATCH / 128), 512, GEMM_SMEM>>>(bia, out);
}

// round 14
// speedup vs baseline: 1.1177x; 1.1177x over previous
#include <cuda_runtime.h>
#include <cuda_fp16.h>
#include <cstdint>
#include <cstddef>
#include <math.h>

#define N_FFT   16000
#define BATCH   512
#define D_IN    2048
#define ODIM    3000
#define OPAD    3072
#define KDIM    16000

// Scratch (device globals — allocation-free per harness rules)
__device__ float2 g_TW[N_FFT];                         // twiddles
__device__ __align__(16) __half g_Zh[BATCH * KDIM];    // 16 MB (z in fp16)
__device__ __align__(16) __half g_Wh[OPAD * KDIM];     // 96 MB (W in fp16)

static __device__ __forceinline__ float2 cmulf(float2 a, float2 b) {
    return make_float2(a.x * b.x - a.y * b.y, a.x * b.y + a.y * b.x);
}
static __device__ __forceinline__ unsigned smem_u32(const void* p) {
    unsigned a;
    asm("{ .reg .u64 t; cvta.to.shared.u64 t, %1; cvt.u32.u64 %0, t; }" : "=r"(a) : "l"(p));
    return a;
}
static __device__ __forceinline__ unsigned swz128(unsigned off) {
    return off ^ ((off >> 3) & 0x70);
}
#define CP_ASYNC16(dst, src) \
    asm volatile("cp.async.cg.shared.global [%0], [%1], 16;" :: "r"(dst), "l"(src))
#define CP_COMMIT() asm volatile("cp.async.commit_group;" ::: "memory")
#define CP_WAIT2()  asm volatile("cp.async.wait_group 2;" ::: "memory")

static __device__ __forceinline__ void ldsm_x4(unsigned addr, unsigned* r) {
    asm volatile("ldmatrix.sync.aligned.m8n8.x4.shared.b16 {%0,%1,%2,%3}, [%4];"
                 : "=r"(r[0]), "=r"(r[1]), "=r"(r[2]), "=r"(r[3]) : "r"(addr));
}
static __device__ __forceinline__ void mma_f16(float* c, const unsigned* a, const unsigned* b) {
    asm volatile(
        "mma.sync.aligned.m16n8k16.row.col.f32.f16.f16.f32 "
        "{%0,%1,%2,%3}, {%4,%5,%6,%7}, {%8,%9}, {%0,%1,%2,%3};"
        : "+f"(c[0]), "+f"(c[1]), "+f"(c[2]), "+f"(c[3])
        : "r"(a[0]), "r"(a[1]), "r"(a[2]), "r"(a[3]), "r"(b[0]), "r"(b[1]));
}

// ---------------------------------------------------------------------------
__global__ void tw_init_kernel() {
    int j = blockIdx.x * blockDim.x + threadIdx.x;
    if (j < N_FFT) {
        double ang = -2.0 * 3.14159265358979323846 * (double)j / (double)N_FFT;
        double s, c;
        sincos(ang, &s, &c);
        g_TW[j] = make_float2((float)c, (float)s);
    }
}

// ---------------------------------------------------------------------------
// W -> fp16 plane (rows >= ODIM zero-filled). One thread = 8 elements.
// ---------------------------------------------------------------------------
__global__ __launch_bounds__(256) void wconv_kernel(const float* __restrict__ Wm) {
    const int SEG = KDIM / 8;                 // 2000
    int lin = blockIdx.x * blockDim.x + threadIdx.x;
    if (lin >= OPAD * SEG) return;
    int r = lin / SEG;
    int s = lin - r * SEG;
    __half2 h[4];
    if (r < ODIM) {
        const float4* p = reinterpret_cast<const float4*>(Wm + (size_t)r * KDIM + s * 8);
        float4 a = p[0], b = p[1];
        h[0] = __floats2half2_rn(a.x, a.y);
        h[1] = __floats2half2_rn(a.z, a.w);
        h[2] = __floats2half2_rn(b.x, b.y);
        h[3] = __floats2half2_rn(b.z, b.w);
    } else {
        h[0] = h[1] = h[2] = h[3] = __floats2half2_rn(0.f, 0.f);
    }
    *reinterpret_cast<uint4*>(g_Wh + (size_t)r * KDIM + s * 8) =
        *reinterpret_cast<uint4*>(h);
}

// ---------------------------------------------------------------------------
// FFT core: Step A (radix-4 x2 + radix-8) + Step C (radix-5 x3, stage 0 folds
// the inter-step twiddle). After core: slot s = q*125 + j holds spectrum index
// k = k1(q) + 128*k2(j), k1(q) = (q>>5)+((q>>3)&3)*4+(q&7)*16, k2(j) = rev5(j).
// ---------------------------------------------------------------------------
template <bool INV>
static __device__ __forceinline__ void fft_core(float2* A, const float2* W125,
                                                int tid, int T) {
    // ---- Step A: radix-4 x2 ----
    {
        const int subs4[2] = {32, 8};
        const int twm[2]   = {125, 500};
#pragma unroll
        for (int s = 0; s < 2; ++s) {
            const int sub = subs4[s];
            const int L = 4 * sub;
            const int tm = twm[s];
            for (int i = tid; i < 4000; i += T) {
                int n2 = i % 125;
                int t  = i / 125;               // 0..31
                int blk = t / sub;
                int j   = t - blk * sub;
                int base = (blk * L + j) * 125 + n2;
                const int st = sub * 125;
                float2 x0v = A[base];
                float2 x1v = A[base + st];
                float2 x2v = A[base + 2 * st];
                float2 x3v = A[base + 3 * st];
                float2 t0 = make_float2(x0v.x + x2v.x, x0v.y + x2v.y);
                float2 t1 = make_float2(x0v.x - x2v.x, x0v.y - x2v.y);
                float2 t2 = make_float2(x1v.x + x3v.x, x1v.y + x3v.y);
                float2 t3 = make_float2(x1v.x - x3v.x, x1v.y - x3v.y);
                float2 it3 = INV ? make_float2(-t3.y, t3.x) : make_float2(t3.y, -t3.x);
                float2 y0 = make_float2(t0.x + t2.x, t0.y + t2.y);
                float2 y2 = make_float2(t0.x - t2.x, t0.y - t2.y);
                float2 y1 = make_float2(t1.x + it3.x, t1.y + it3.y);
                float2 y3 = make_float2(t1.x - it3.x, t1.y - it3.y);
                float2 w1 = g_TW[j * tm];
                float2 w2 = g_TW[2 * j * tm];
                float2 w3 = g_TW[3 * j * tm];
                if (INV) { w1.y = -w1.y; w2.y = -w2.y; w3.y = -w3.y; }
                A[base]          = y0;
                A[base + st]     = cmulf(y1, w1);
                A[base + 2 * st] = cmulf(y2, w2);
                A[base + 3 * st] = cmulf(y3, w3);
            }
            __syncthreads();
        }
    }
    // ---- Step A final: radix-8 (direct 8-pt DFT, no post-twiddles) ----
    {
        const float h8 = 0.70710678118654752440f;
        for (int i = tid; i < 2000; i += T) {
            int n2 = i % 125;
            int m  = i / 125;                  // 0..15
            int base = m * 1000 + n2;
            float2 x[8];
#pragma unroll
            for (int e = 0; e < 8; ++e) x[e] = A[base + e * 125];
            float2 s0 = make_float2(x[0].x + x[4].x, x[0].y + x[4].y);
            float2 s1 = make_float2(x[0].x - x[4].x, x[0].y - x[4].y);
            float2 s2 = make_float2(x[2].x + x[6].x, x[2].y + x[6].y);
            float2 s3 = make_float2(x[2].x - x[6].x, x[2].y - x[6].y);
            float2 E0 = make_float2(s0.x + s2.x, s0.y + s2.y);
            float2 E2 = make_float2(s0.x - s2.x, s0.y - s2.y);
            float2 E1 = INV ? make_float2(s1.x - s3.y, s1.y + s3.x)
                            : make_float2(s1.x + s3.y, s1.y - s3.x);
            float2 E3 = INV ? make_float2(s1.x + s3.y, s1.y - s3.x)
                            : make_float2(s1.x - s3.y, s1.y + s3.x);
            float2 t0 = make_float2(x[1].x + x[5].x, x[1].y + x[5].y);
            float2 t1 = make_float2(x[1].x - x[5].x, x[1].y - x[5].y);
            float2 t2 = make_float2(x[3].x + x[7].x, x[3].y + x[7].y);
            float2 t3 = make_float2(x[3].x - x[7].x, x[3].y - x[7].y);
            float2 O0 = make_float2(t0.x + t2.x, t0.y + t2.y);
            float2 O2 = make_float2(t0.x - t2.x, t0.y - t2.y);
            float2 O1 = INV ? make_float2(t1.x - t3.y, t1.y + t3.x)
                            : make_float2(t1.x + t3.y, t1.y - t3.x);
            float2 O3 = INV ? make_float2(t1.x + t3.y, t1.y - t3.x)
                            : make_float2(t1.x - t3.y, t1.y + t3.x);
            float2 W1O, W2O, W3O;
            if (!INV) {
                W1O = make_float2(h8 * (O1.x + O1.y), h8 * (O1.y - O1.x));
                W2O = make_float2(O2.y, -O2.x);
                W3O = make_float2(-h8 * (O3.x - O3.y), -h8 * (O3.x + O3.y));
            } else {
                W1O = make_float2(h8 * (O1.x - O1.y), h8 * (O1.y + O1.x));
                W2O = make_float2(-O2.y, O2.x);
                W3O = make_float2(-h8 * (O3.x + O3.y), -h8 * (O3.y - O3.x));
            }
            A[base]           = make_float2(E0.x + O0.x, E0.y + O0.y);
            A[base + 125]     = make_float2(E1.x + W1O.x, E1.y + W1O.y);
            A[base + 250]     = make_float2(E2.x + W2O.x, E2.y + W2O.y);
            A[base + 375]     = make_float2(E3.x + W3O.x, E3.y + W3O.y);
            A[base + 500]     = make_float2(E0.x - O0.x, E0.y - O0.y);
            A[base + 625]     = make_float2(E1.x - W1O.x, E1.y - W1O.y);
            A[base + 750]     = make_float2(E2.x - W2O.x, E2.y - W2O.y);
            A[base + 875]     = make_float2(E3.x - W3O.x, E3.y - W3O.y);
        }
        __syncthreads();
    }
    // ---- Step C: 3 radix-5 DIF stages; stage 0 folds inter-step twiddle ----
    {
        const float c1 = 0.309016994374947424f;
        const float c2 = -0.809016994374947424f;
        const float S1 = INV ? -0.951056516295153572f : 0.951056516295153572f;
        const float S2 = INV ? -0.587785252292473129f : 0.587785252292473129f;
        const int Ls[3]   = {125, 25, 5};
        const int subs[3] = {25, 5, 1};
        const int fs[3]   = {1, 5, 25};
#pragma unroll
        for (int s = 0; s < 3; ++s) {
            const int L = Ls[s], sub = subs[s], f = fs[s];
            for (int i = tid; i < 3200; i += T) {
                int q = i / 25;
                int t = i - q * 25;
                int blk = t / sub;
                int j   = t - blk * sub;
                int base = q * 125 + blk * L + j;
                float2 x0v = A[base];
                float2 x1v = A[base + sub];
                float2 x2v = A[base + 2 * sub];
                float2 x3v = A[base + 3 * sub];
                float2 x4v = A[base + 4 * sub];
                if (s == 0) {
                    int k1 = (q >> 5) + ((q >> 3) & 3) * 4 + (q & 7) * 16;
                    float2 b0 = g_TW[j * k1];
                    float2 b1 = g_TW[(j + 25) * k1];
                    float2 b2 = g_TW[(j + 50) * k1];
                    float2 b3 = g_TW[(j + 75) * k1];
                    float2 b4 = g_TW[(j + 100) * k1];
                    if (INV) { b0.y = -b0.y; b1.y = -b1.y; b2.y = -b2.y; b3.y = -b3.y; b4.y = -b4.y; }
                    x0v = cmulf(x0v, b0);
                    x1v = cmulf(x1v, b1);
                    x2v = cmulf(x2v, b2);
                    x3v = cmulf(x3v, b3);
                    x4v = cmulf(x4v, b4);
                }
                float t1x = x1v.x + x4v.x, t1y = x1v.y + x4v.y;
                float t2x = x2v.x + x3v.x, t2y = x2v.y + x3v.y;
                float t3x = x1v.x - x4v.x, t3y = x1v.y - x4v.y;
                float t4x = x2v.x - x3v.x, t4y = x2v.y - x3v.y;
                float2 y0 = make_float2(x0v.x + t1x + t2x, x0v.y + t1y + t2y);
                float ax = x0v.x + c1 * t1x + c2 * t2x;
                float ay = x0v.y + c1 * t1y + c2 * t2y;
                float bx = S1 * t3x + S2 * t4x;
                float by = S1 * t3y + S2 * t4y;
                float dx = x0v.x + c2 * t1x + c1 * t2x;
                float dy = x0v.y + c2 * t1y + c1 * t2y;
                float ex = S2 * t3x - S1 * t4x;
                float ey = S2 * t3y - S1 * t4y;
                float2 y1 = make_float2(ax + by, ay - bx);
                float2 y4 = make_float2(ax - by, ay + bx);
                float2 y2 = make_float2(dx + ey, dy - ex);
                float2 y3 = make_float2(dx - ey, dy + ex);
                int jf = j * f;
                float2 w1 = W125[jf],  w2 = W125[2 * jf], w3 = W125[3 * jf], w4 = W125[4 * jf];
                if (INV) { w1.y = -w1.y; w2.y = -w2.y; w3.y = -w3.y; w4.y = -w4.y; }
                A[base]           = y0;
                A[base + sub]     = cmulf(y1, w1);
                A[base + 2 * sub] = cmulf(y2, w2);
                A[base + 3 * sub] = cmulf(y3, w3);
                A[base + 4 * sub] = cmulf(y4, w4);
            }
            __syncthreads();
        }
    }
}

// slot of spectrum index k in post-core layout
static __device__ __forceinline__ int slot_of(int k) {
    int k1 = k & 127;
    int k2 = k >> 7;
    int q = (k1 & 3) * 32 + ((k1 >> 2) & 3) * 8 + (k1 >> 4);
    int j = (k2 / 25) + ((k2 / 5) % 5) * 5 + (k2 % 5) * 25;
    return q * 125 + j;
}

// ---------------------------------------------------------------------------
// Fully fused: sketch build -> fwd FFT -> pointwise (conj symmetry) ->
// inverse FFT -> fp16 z store. One CTA (1024 thr) per batch row.
// ---------------------------------------------------------------------------
__global__ __launch_bounds__(1024) void fused_fft_kernel(
    const float* __restrict__ x0, const float* __restrict__ x1,
    const float* __restrict__ s1, const float* __restrict__ s2,
    const int* __restrict__ h1, const int* __restrict__ h2) {
    extern __shared__ float2 sm[];
    float2* A    = sm;            // 16000
    float2* W125 = sm + N_FFT;    // 125

    const int b   = blockIdx.x;
    const int tid = threadIdx.x;
    const int T   = blockDim.x;   // 1024

    for (int k = tid; k < N_FFT; k += T) A[k] = make_float2(0.f, 0.f);
    for (int m = tid; m < 125; m += T) W125[m] = g_TW[128 * m];
    __syncthreads();
    for (int a = tid; a < D_IN; a += T) {
        float v1 = s1[a] * x0[b * D_IN + a];
        float v2 = s2[a] * x1[b * D_IN + a];
        atomicAdd(&A[h1[a]].x, v1);
        atomicAdd(&A[h2[a]].y, v2);
    }
    __syncthreads();

    fft_core<false>(A, W125, tid, T);

    // pointwise: Z[k] = F1[k]*F2[k]; Z[N-k] = conj(Z[k])
    {
        float2 Zreg[8];
#pragma unroll
        for (int it = 0; it < 8; ++it) {
            int k = tid + it * T;
            if (k <= 8000) {
                int sA = slot_of(k);
                int kn = (k == 0) ? 0 : N_FFT - k;
                int sB = (kn == k) ? sA : slot_of(kn);
                float2 C = A[sA], D = A[sB];
                float2 F1 = make_float2(0.5f * (C.x + D.x), 0.5f * (C.y - D.y));
                float2 F2 = make_float2(0.5f * (C.y + D.y), 0.5f * (D.x - C.x));
                Zreg[it] = cmulf(F1, F2);
            }
        }
        __syncthreads();
#pragma unroll
        for (int it = 0; it < 8; ++it) {
            int k = tid + it * T;
            if (k <= 8000) {
                float2 Z = Zreg[it];
                A[k] = Z;
                if (k > 0 && k < 8000)
                    A[N_FFT - k] = make_float2(Z.x, -Z.y);
            }
        }
        __syncthreads();
    }

    fft_core<true>(A, W125, tid, T);

    const float invN = 1.0f / (float)N_FFT;
    for (int k = tid; k < N_FFT; k += T) {
        float2 v = A[slot_of(k)];
        g_Zh[(size_t)b * KDIM + k] = __float2half_rn(v.x * invN);
    }
}

// ---------------------------------------------------------------------------
// fp16 single-term HMMA GEMM:  out = relu(zh @ wh^T + b)
// Tile 128x96, k-chunk 64, grid (32,4)=128 CTAs, 256 thr (8 warps, 4m x 2n),
// 4-stage cp.async pipeline + ks-level fragment double buffering.
// ---------------------------------------------------------------------------
#define GTK 64
#define GITERS (KDIM / GTK)          // 250
#define A_PL 16384
#define B_PL 12288
#define STG_BYTES (A_PL + B_PL)      // 28672
#define NST 4
#define GEMM_SMEM (NST * STG_BYTES)  // 114688

static __device__ __forceinline__ void gemm_issue_stage(unsigned sb, int tid, int k0,
                                                        int m0, int n0g) {
    const char* zh = reinterpret_cast<const char*>(g_Zh);
    const char* wh = reinterpret_cast<const char*>(g_Wh);
#pragma unroll
    for (int i = 0; i < 4; ++i) {                 // A: 128 rows x 8 segs
        int lin = i * 256 + tid;
        int r = lin >> 3, seg = lin & 7;
        unsigned d = sb + swz128((unsigned)(r * 128 + seg * 16));
        size_t so = ((size_t)(m0 + r) * KDIM + k0 + seg * 8) * 2;
        CP_ASYNC16(d, zh + so);
    }
#pragma unroll
    for (int i = 0; i < 3; ++i) {                 // B: 96 rows x 8 segs
        int lin = i * 256 + tid;
        int r = lin >> 3, seg = lin & 7;
        unsigned d = sb + A_PL + swz128((unsigned)(r * 128 + seg * 16));
        size_t so = ((size_t)(n0g + r) * KDIM + k0 + seg * 8) * 2;
        CP_ASYNC16(d, wh + so);
    }
}

__global__ __launch_bounds__(256, 1) void gemm_hmma_kernel(const float* __restrict__ bias,
                                                           float* __restrict__ out) {
    extern __shared__ char gsm[];
    const unsigned sbase = smem_u32(gsm);
    const int tid  = threadIdx.x;
    const int lane = tid & 31;
    const int wid  = tid >> 5;
    const int wm   = wid >> 1;          // 0..3 -> 32 m rows each
    const int wn   = wid & 1;           // 0..1 -> 48 n cols each
    const int n0 = blockIdx.x * 96;
    const int m0 = blockIdx.y * 128;

    float acc[2][6][4];
#pragma unroll
    for (int i = 0; i < 2; ++i)
#pragma unroll
        for (int j = 0; j < 6; ++j)
#pragma unroll
            for (int e = 0; e < 4; ++e) acc[i][j][e] = 0.f;

    gemm_issue_stage(sbase, tid, 0, m0, n0);
    CP_COMMIT();
    gemm_issue_stage(sbase + STG_BYTES, tid, GTK, m0, n0);
    CP_COMMIT();
    gemm_issue_stage(sbase + 2 * STG_BYTES, tid, 2 * GTK, m0, n0);
    CP_COMMIT();

    const unsigned aRowSel = (unsigned)(lane & 15) * 128 + ((unsigned)(lane >> 4) << 4);
    const unsigned bRowSel = (unsigned)((lane & 7) | (((lane >> 4) & 1) << 3)) * 128 +
                             (((unsigned)(lane >> 3) & 1) << 4);
    const unsigned aBase = (unsigned)(wm * 32) * 128 + aRowSel;       // + mf*16*128 + ks*32
    const unsigned bBase = (unsigned)(wn * 48) * 128 + bRowSel;       // + g*16*128 + ks*32

    unsigned Af[2][2][4];    // [buf][mf]
    unsigned Bf[2][3][4];    // [buf][g]

    for (int c = 0; c < GITERS; ++c) {
        CP_WAIT2();
        __syncthreads();
        if (c + 3 < GITERS) {
            gemm_issue_stage(sbase + ((c + 3) & 3) * STG_BYTES, tid, (c + 3) * GTK, m0, n0);
        }
        CP_COMMIT();

        const unsigned Ab = sbase + (c & 3) * STG_BYTES;
        const unsigned Bb = Ab + A_PL;

        // load ks=0 fragments into buffer 0
#pragma unroll
        for (int mf = 0; mf < 2; ++mf)
            ldsm_x4(Ab + swz128(aBase + mf * (16 * 128)), Af[0][mf]);
#pragma unroll
        for (int g = 0; g < 3; ++g)
            ldsm_x4(Bb + swz128(bBase + g * (16 * 128)), Bf[0][g]);

#pragma unroll
        for (int ks = 0; ks < 4; ++ks) {
            const int cur = ks & 1;
            const int nxt = cur ^ 1;
            if (ks < 3) {
                // prefetch ks+1 fragments while MMAs of ks run
#pragma unroll
                for (int mf = 0; mf < 2; ++mf)
                    ldsm_x4(Ab + swz128(aBase + mf * (16 * 128) + (ks + 1) * 32), Af[nxt][mf]);
#pragma unroll
                for (int g = 0; g < 3; ++g)
                    ldsm_x4(Bb + swz128(bBase + g * (16 * 128) + (ks + 1) * 32), Bf[nxt][g]);
            }
#pragma unroll
            for (int mf = 0; mf < 2; ++mf)
#pragma unroll
                for (int nf = 0; nf < 6; ++nf)
                    mma_f16(acc[mf][nf], Af[cur][mf], &Bf[cur][nf >> 1][(nf & 1) * 2]);
        }
        // NOTE: no trailing __syncthreads — the top-of-loop WAIT2+sync orders
        // compute-done on stage (c-1)&3 before the cp.async overwrite of (c+3)&3.
    }

    // ---- epilogue: bias + relu ----
#pragma unroll
    for (int mf = 0; mf < 2; ++mf) {
        int mlo = m0 + wm * 32 + mf * 16 + (lane >> 2);
#pragma unroll
        for (int nf = 0; nf < 6; ++nf) {
            int n = n0 + wn * 48 + nf * 8 + 2 * (lane & 3);
            if (n < ODIM) {
                float b0 = bias[n], b1 = bias[n + 1];
                float2 v0, v1;
                v0.x = fmaxf(acc[mf][nf][0] + b0, 0.f);
                v0.y = fmaxf(acc[mf][nf][1] + b1, 0.f);
                v1.x = fmaxf(acc[mf][nf][2] + b0, 0.f);
                v1.y = fmaxf(acc[mf][nf][3] + b1, 0.f);
                *reinterpret_cast<float2*>(out + (size_t)mlo * ODIM + n) = v0;
                *reinterpret_cast<float2*>(out + (size_t)(mlo + 8) * ODIM + n) = v1;
            }
        }
    }
}

// ---------------------------------------------------------------------------
extern "C" void kernel_launch(void* const* d_in, const int* in_sizes, int n_in,
                              void* d_out, int out_size) {
    const float* x0  = (const float*)d_in[0];
    const float* x1  = (const float*)d_in[1];
    const float* s1  = (const float*)d_in[2];
    const float* s2  = (const float*)d_in[3];
    const float* Wm  = (const float*)d_in[4];
    const float* bia = (const float*)d_in[5];
    const int*   h1  = (const int*)d_in[6];
    const int*   h2  = (const int*)d_in[7];
    float* out = (float*)d_out;

    // side stream + events for wconv overlap (created on first, uncaptured call)
    static cudaStream_t side = nullptr;
    static cudaEvent_t evFork = nullptr, evJoin = nullptr;
    if (!side) {
        cudaStreamCreateWithFlags(&side, cudaStreamNonBlocking);
        cudaEventCreateWithFlags(&evFork, cudaEventDisableTiming);
        cudaEventCreateWithFlags(&evJoin, cudaEventDisableTiming);
    }

    const int FFT_SMEM = (N_FFT + 128) * (int)sizeof(float2);  // 129 KB
    cudaFuncSetAttribute(fused_fft_kernel, cudaFuncAttributeMaxDynamicSharedMemorySize, FFT_SMEM);
    cudaFuncSetAttribute(gemm_hmma_kernel, cudaFuncAttributeMaxDynamicSharedMemorySize, GEMM_SMEM);

    // fork: wconv on side stream (DRAM-bound; overlaps compute-bound FFT)
    cudaEventRecord(evFork, 0);
    cudaStreamWaitEvent(side, evFork, 0);
    const int wthreads = OPAD * (KDIM / 8);
    wconv_kernel<<<(wthreads + 255) / 256, 256, 0, side>>>(Wm);
    cudaEventRecord(evJoin, side);

    tw_init_kernel<<<(N_FFT + 255) / 256, 256>>>();

    fused_fft_kernel<<<BATCH, 1024, FFT_SMEM>>>(x0, x1, s1, s2, h1, h2);

    // join: gemm needs g_Wh
    cudaStreamWaitEvent(0, evJoin, 0);
    gemm_hmma_kernel<<<dim3((ODIM + 95) / 96, BATCH / 128), 256, GEMM_SMEM>>>(bia, out);
}

// round 15
// speedup vs baseline: 1.1642x; 1.0416x over previous
#include <cuda_runtime.h>
#include <cuda_fp16.h>
#include <cstdint>
#include <cstddef>
#include <math.h>

#define N_FFT   16000
#define BATCH   512
#define D_IN    2048
#define ODIM    3000
#define OPAD    3072
#define KDIM    16000

// Scratch (device globals — allocation-free per harness rules)
__device__ float2 g_TW[N_FFT];                         // twiddles
__device__ __align__(16) __half g_Zh[BATCH * KDIM];    // 16 MB (z in fp16)
__device__ __align__(16) __half g_Wh[OPAD * KDIM];     // 96 MB (W in fp16)

static __device__ __forceinline__ float2 cmulf(float2 a, float2 b) {
    return make_float2(a.x * b.x - a.y * b.y, a.x * b.y + a.y * b.x);
}
static __device__ __forceinline__ unsigned smem_u32(const void* p) {
    unsigned a;
    asm("{ .reg .u64 t; cvta.to.shared.u64 t, %1; cvt.u32.u64 %0, t; }" : "=r"(a) : "l"(p));
    return a;
}
static __device__ __forceinline__ unsigned swz128(unsigned off) {
    return off ^ ((off >> 3) & 0x70);
}
#define CP_ASYNC16(dst, src) \
    asm volatile("cp.async.cg.shared.global [%0], [%1], 16;" :: "r"(dst), "l"(src))
#define CP_COMMIT() asm volatile("cp.async.commit_group;" ::: "memory")
#define CP_WAIT2()  asm volatile("cp.async.wait_group 2;" ::: "memory")

static __device__ __forceinline__ void ldsm_x4(unsigned addr, unsigned* r) {
    asm volatile("ldmatrix.sync.aligned.m8n8.x4.shared.b16 {%0,%1,%2,%3}, [%4];"
                 : "=r"(r[0]), "=r"(r[1]), "=r"(r[2]), "=r"(r[3]) : "r"(addr));
}
static __device__ __forceinline__ void mma_f16(float* c, const unsigned* a, const unsigned* b) {
    asm volatile(
        "mma.sync.aligned.m16n8k16.row.col.f32.f16.f16.f32 "
        "{%0,%1,%2,%3}, {%4,%5,%6,%7}, {%8,%9}, {%0,%1,%2,%3};"
        : "+f"(c[0]), "+f"(c[1]), "+f"(c[2]), "+f"(c[3])
        : "r"(a[0]), "r"(a[1]), "r"(a[2]), "r"(a[3]), "r"(b[0]), "r"(b[1]));
}

// ---------------------------------------------------------------------------
__global__ void tw_init_kernel() {
    int j = blockIdx.x * blockDim.x + threadIdx.x;
    if (j < N_FFT) {
        double ang = -2.0 * 3.14159265358979323846 * (double)j / (double)N_FFT;
        double s, c;
        sincos(ang, &s, &c);
        g_TW[j] = make_float2((float)c, (float)s);
    }
}

// ---------------------------------------------------------------------------
// W -> fp16 plane (rows >= ODIM zero-filled). One thread = 8 elements.
// ---------------------------------------------------------------------------
__global__ __launch_bounds__(256) void wconv_kernel(const float* __restrict__ Wm) {
    const int SEG = KDIM / 8;                 // 2000
    int lin = blockIdx.x * blockDim.x + threadIdx.x;
    if (lin >= OPAD * SEG) return;
    int r = lin / SEG;
    int s = lin - r * SEG;
    __half2 h[4];
    if (r < ODIM) {
        const float4* p = reinterpret_cast<const float4*>(Wm + (size_t)r * KDIM + s * 8);
        float4 a = p[0], b = p[1];
        h[0] = __floats2half2_rn(a.x, a.y);
        h[1] = __floats2half2_rn(a.z, a.w);
        h[2] = __floats2half2_rn(b.x, b.y);
        h[3] = __floats2half2_rn(b.z, b.w);
    } else {
        h[0] = h[1] = h[2] = h[3] = __floats2half2_rn(0.f, 0.f);
    }
    *reinterpret_cast<uint4*>(g_Wh + (size_t)r * KDIM + s * 8) =
        *reinterpret_cast<uint4*>(h);
}

// ---------------------------------------------------------------------------
// FFT core: Step A (radix-4 x2 + radix-8) + Step C (radix-5 x3, stage 0 folds
// the inter-step twiddle). After core: slot s = q*125 + j holds spectrum index
// k = k1(q) + 128*k2(j), k1(q) = (q>>5)+((q>>3)&3)*4+(q&7)*16, k2(j) = rev5(j).
// ---------------------------------------------------------------------------
template <bool INV>
static __device__ __forceinline__ void fft_core(float2* A, const float2* W125,
                                                int tid, int T) {
    // ---- Step A: radix-4 x2 ----
    {
        const int subs4[2] = {32, 8};
        const int twm[2]   = {125, 500};
#pragma unroll
        for (int s = 0; s < 2; ++s) {
            const int sub = subs4[s];
            const int L = 4 * sub;
            const int tm = twm[s];
            for (int i = tid; i < 4000; i += T) {
                int n2 = i % 125;
                int t  = i / 125;               // 0..31
                int blk = t / sub;
                int j   = t - blk * sub;
                int base = (blk * L + j) * 125 + n2;
                const int st = sub * 125;
                float2 x0v = A[base];
                float2 x1v = A[base + st];
                float2 x2v = A[base + 2 * st];
                float2 x3v = A[base + 3 * st];
                float2 t0 = make_float2(x0v.x + x2v.x, x0v.y + x2v.y);
                float2 t1 = make_float2(x0v.x - x2v.x, x0v.y - x2v.y);
                float2 t2 = make_float2(x1v.x + x3v.x, x1v.y + x3v.y);
                float2 t3 = make_float2(x1v.x - x3v.x, x1v.y - x3v.y);
                float2 it3 = INV ? make_float2(-t3.y, t3.x) : make_float2(t3.y, -t3.x);
                float2 y0 = make_float2(t0.x + t2.x, t0.y + t2.y);
                float2 y2 = make_float2(t0.x - t2.x, t0.y - t2.y);
                float2 y1 = make_float2(t1.x + it3.x, t1.y + it3.y);
                float2 y3 = make_float2(t1.x - it3.x, t1.y - it3.y);
                float2 w1 = g_TW[j * tm];
                float2 w2 = g_TW[2 * j * tm];
                float2 w3 = g_TW[3 * j * tm];
                if (INV) { w1.y = -w1.y; w2.y = -w2.y; w3.y = -w3.y; }
                A[base]          = y0;
                A[base + st]     = cmulf(y1, w1);
                A[base + 2 * st] = cmulf(y2, w2);
                A[base + 3 * st] = cmulf(y3, w3);
            }
            __syncthreads();
        }
    }
    // ---- Step A final: radix-8 (direct 8-pt DFT, no post-twiddles) ----
    {
        const float h8 = 0.70710678118654752440f;
        for (int i = tid; i < 2000; i += T) {
            int n2 = i % 125;
            int m  = i / 125;                  // 0..15
            int base = m * 1000 + n2;
            float2 x[8];
#pragma unroll
            for (int e = 0; e < 8; ++e) x[e] = A[base + e * 125];
            float2 s0 = make_float2(x[0].x + x[4].x, x[0].y + x[4].y);
            float2 s1 = make_float2(x[0].x - x[4].x, x[0].y - x[4].y);
            float2 s2 = make_float2(x[2].x + x[6].x, x[2].y + x[6].y);
            float2 s3 = make_float2(x[2].x - x[6].x, x[2].y - x[6].y);
            float2 E0 = make_float2(s0.x + s2.x, s0.y + s2.y);
            float2 E2 = make_float2(s0.x - s2.x, s0.y - s2.y);
            float2 E1 = INV ? make_float2(s1.x - s3.y, s1.y + s3.x)
                            : make_float2(s1.x + s3.y, s1.y - s3.x);
            float2 E3 = INV ? make_float2(s1.x + s3.y, s1.y - s3.x)
                            : make_float2(s1.x - s3.y, s1.y + s3.x);
            float2 t0 = make_float2(x[1].x + x[5].x, x[1].y + x[5].y);
            float2 t1 = make_float2(x[1].x - x[5].x, x[1].y - x[5].y);
            float2 t2 = make_float2(x[3].x + x[7].x, x[3].y + x[7].y);
            float2 t3 = make_float2(x[3].x - x[7].x, x[3].y - x[7].y);
            float2 O0 = make_float2(t0.x + t2.x, t0.y + t2.y);
            float2 O2 = make_float2(t0.x - t2.x, t0.y - t2.y);
            float2 O1 = INV ? make_float2(t1.x - t3.y, t1.y + t3.x)
                            : make_float2(t1.x + t3.y, t1.y - t3.x);
            float2 O3 = INV ? make_float2(t1.x + t3.y, t1.y - t3.x)
                            : make_float2(t1.x - t3.y, t1.y + t3.x);
            float2 W1O, W2O, W3O;
            if (!INV) {
                W1O = make_float2(h8 * (O1.x + O1.y), h8 * (O1.y - O1.x));
                W2O = make_float2(O2.y, -O2.x);
                W3O = make_float2(-h8 * (O3.x - O3.y), -h8 * (O3.x + O3.y));
            } else {
                W1O = make_float2(h8 * (O1.x - O1.y), h8 * (O1.y + O1.x));
                W2O = make_float2(-O2.y, O2.x);
                W3O = make_float2(-h8 * (O3.x + O3.y), -h8 * (O3.y - O3.x));
            }
            A[base]           = make_float2(E0.x + O0.x, E0.y + O0.y);
            A[base + 125]     = make_float2(E1.x + W1O.x, E1.y + W1O.y);
            A[base + 250]     = make_float2(E2.x + W2O.x, E2.y + W2O.y);
            A[base + 375]     = make_float2(E3.x + W3O.x, E3.y + W3O.y);
            A[base + 500]     = make_float2(E0.x - O0.x, E0.y - O0.y);
            A[base + 625]     = make_float2(E1.x - W1O.x, E1.y - W1O.y);
            A[base + 750]     = make_float2(E2.x - W2O.x, E2.y - W2O.y);
            A[base + 875]     = make_float2(E3.x - W3O.x, E3.y - W3O.y);
        }
        __syncthreads();
    }
    // ---- Step C: 3 radix-5 DIF stages; stage 0 folds inter-step twiddle ----
    {
        const float c1 = 0.309016994374947424f;
        const float c2 = -0.809016994374947424f;
        const float S1 = INV ? -0.951056516295153572f : 0.951056516295153572f;
        const float S2 = INV ? -0.587785252292473129f : 0.587785252292473129f;
        const int Ls[3]   = {125, 25, 5};
        const int subs[3] = {25, 5, 1};
        const int fs[3]   = {1, 5, 25};
#pragma unroll
        for (int s = 0; s < 3; ++s) {
            const int L = Ls[s], sub = subs[s], f = fs[s];
            for (int i = tid; i < 3200; i += T) {
                int q = i / 25;
                int t = i - q * 25;
                int blk = t / sub;
                int j   = t - blk * sub;
                int base = q * 125 + blk * L + j;
                float2 x0v = A[base];
                float2 x1v = A[base + sub];
                float2 x2v = A[base + 2 * sub];
                float2 x3v = A[base + 3 * sub];
                float2 x4v = A[base + 4 * sub];
                if (s == 0) {
                    int k1 = (q >> 5) + ((q >> 3) & 3) * 4 + (q & 7) * 16;
                    float2 b0 = g_TW[j * k1];
                    float2 b1 = g_TW[(j + 25) * k1];
                    float2 b2 = g_TW[(j + 50) * k1];
                    float2 b3 = g_TW[(j + 75) * k1];
                    float2 b4 = g_TW[(j + 100) * k1];
                    if (INV) { b0.y = -b0.y; b1.y = -b1.y; b2.y = -b2.y; b3.y = -b3.y; b4.y = -b4.y; }
                    x0v = cmulf(x0v, b0);
                    x1v = cmulf(x1v, b1);
                    x2v = cmulf(x2v, b2);
                    x3v = cmulf(x3v, b3);
                    x4v = cmulf(x4v, b4);
                }
                float t1x = x1v.x + x4v.x, t1y = x1v.y + x4v.y;
                float t2x = x2v.x + x3v.x, t2y = x2v.y + x3v.y;
                float t3x = x1v.x - x4v.x, t3y = x1v.y - x4v.y;
                float t4x = x2v.x - x3v.x, t4y = x2v.y - x3v.y;
                float2 y0 = make_float2(x0v.x + t1x + t2x, x0v.y + t1y + t2y);
                float ax = x0v.x + c1 * t1x + c2 * t2x;
                float ay = x0v.y + c1 * t1y + c2 * t2y;
                float bx = S1 * t3x + S2 * t4x;
                float by = S1 * t3y + S2 * t4y;
                float dx = x0v.x + c2 * t1x + c1 * t2x;
                float dy = x0v.y + c2 * t1y + c1 * t2y;
                float ex = S2 * t3x - S1 * t4x;
                float ey = S2 * t3y - S1 * t4y;
                float2 y1 = make_float2(ax + by, ay - bx);
                float2 y4 = make_float2(ax - by, ay + bx);
                float2 y2 = make_float2(dx + ey, dy - ex);
                float2 y3 = make_float2(dx - ey, dy + ex);
                int jf = j * f;
                float2 w1 = W125[jf],  w2 = W125[2 * jf], w3 = W125[3 * jf], w4 = W125[4 * jf];
                if (INV) { w1.y = -w1.y; w2.y = -w2.y; w3.y = -w3.y; w4.y = -w4.y; }
                A[base]           = y0;
                A[base + sub]     = cmulf(y1, w1);
                A[base + 2 * sub] = cmulf(y2, w2);
                A[base + 3 * sub] = cmulf(y3, w3);
                A[base + 4 * sub] = cmulf(y4, w4);
            }
            __syncthreads();
        }
    }
}

// slot of spectrum index k in post-core layout
static __device__ __forceinline__ int slot_of(int k) {
    int k1 = k & 127;
    int k2 = k >> 7;
    int q = (k1 & 3) * 32 + ((k1 >> 2) & 3) * 8 + (k1 >> 4);
    int j = (k2 / 25) + ((k2 / 5) % 5) * 5 + (k2 % 5) * 25;
    return q * 125 + j;
}

// ---------------------------------------------------------------------------
// Fully fused: sketch build -> fwd FFT -> pointwise (conj symmetry) ->
// inverse FFT -> fp16 z store. One CTA (1024 thr) per batch row.
// ---------------------------------------------------------------------------
__global__ __launch_bounds__(1024) void fused_fft_kernel(
    const float* __restrict__ x0, const float* __restrict__ x1,
    const float* __restrict__ s1, const float* __restrict__ s2,
    const int* __restrict__ h1, const int* __restrict__ h2) {
    extern __shared__ float2 sm[];
    float2* A    = sm;            // 16000
    float2* W125 = sm + N_FFT;    // 125

    const int b   = blockIdx.x;
    const int tid = threadIdx.x;
    const int T   = blockDim.x;   // 1024

    for (int k = tid; k < N_FFT; k += T) A[k] = make_float2(0.f, 0.f);
    for (int m = tid; m < 125; m += T) W125[m] = g_TW[128 * m];
    __syncthreads();
    for (int a = tid; a < D_IN; a += T) {
        float v1 = s1[a] * x0[b * D_IN + a];
        float v2 = s2[a] * x1[b * D_IN + a];
        atomicAdd(&A[h1[a]].x, v1);
        atomicAdd(&A[h2[a]].y, v2);
    }
    __syncthreads();

    fft_core<false>(A, W125, tid, T);

    // pointwise: Z[k] = F1[k]*F2[k]; Z[N-k] = conj(Z[k])
    {
        float2 Zreg[8];
#pragma unroll
        for (int it = 0; it < 8; ++it) {
            int k = tid + it * T;
            if (k <= 8000) {
                int sA = slot_of(k);
                int kn = (k == 0) ? 0 : N_FFT - k;
                int sB = (kn == k) ? sA : slot_of(kn);
                float2 C = A[sA], D = A[sB];
                float2 F1 = make_float2(0.5f * (C.x + D.x), 0.5f * (C.y - D.y));
                float2 F2 = make_float2(0.5f * (C.y + D.y), 0.5f * (D.x - C.x));
                Zreg[it] = cmulf(F1, F2);
            }
        }
        __syncthreads();
#pragma unroll
        for (int it = 0; it < 8; ++it) {
            int k = tid + it * T;
            if (k <= 8000) {
                float2 Z = Zreg[it];
                A[k] = Z;
                if (k > 0 && k < 8000)
                    A[N_FFT - k] = make_float2(Z.x, -Z.y);
            }
        }
        __syncthreads();
    }

    fft_core<true>(A, W125, tid, T);

    const float invN = 1.0f / (float)N_FFT;
    for (int k = tid; k < N_FFT; k += T) {
        float2 v = A[slot_of(k)];
        g_Zh[(size_t)b * KDIM + k] = __float2half_rn(v.x * invN);
    }
}

// ---------------------------------------------------------------------------
// fp16 single-term HMMA GEMM:  out = relu(zh @ wh^T + b)
// Tile 128x96, k-chunk 128 (2 sub-stages of 64), grid (32,4)=128 CTAs,
// 256 thr (8 warps, 4m x 2n), 4-stage cp.async pipeline, cross-chunk
// fragment prefetch (stage c+1 guaranteed resident via issue-then-WAIT2).
// ---------------------------------------------------------------------------
#define GTK 128
#define GITERS (KDIM / GTK)          // 125
#define A_PL 16384
#define B_PL 12288
#define SUB_BYTES (A_PL + B_PL)      // 28672
#define STG_BYTES (2 * SUB_BYTES)    // 57344
#define NST 4
#define GEMM_SMEM (NST * STG_BYTES)  // 229376

static __device__ __forceinline__ void gemm_issue_stage(unsigned sb, int tid, int k0,
                                                        int m0, int n0g) {
    const char* zh = reinterpret_cast<const char*>(g_Zh);
    const char* wh = reinterpret_cast<const char*>(g_Wh);
#pragma unroll
    for (int i = 0; i < 8; ++i) {                 // A: 128 rows x 16 segs
        int lin = i * 256 + tid;
        int r = lin >> 4, seg = lin & 15;
        int kk = seg >> 3, s8 = seg & 7;
        unsigned d = sb + kk * SUB_BYTES + swz128((unsigned)(r * 128 + s8 * 16));
        size_t so = ((size_t)(m0 + r) * KDIM + k0 + seg * 8) * 2;
        CP_ASYNC16(d, zh + so);
    }
#pragma unroll
    for (int i = 0; i < 6; ++i) {                 // B: 96 rows x 16 segs
        int lin = i * 256 + tid;
        int r = lin >> 4, seg = lin & 15;
        int kk = seg >> 3, s8 = seg & 7;
        unsigned d = sb + kk * SUB_BYTES + A_PL + swz128((unsigned)(r * 128 + s8 * 16));
        size_t so = ((size_t)(n0g + r) * KDIM + k0 + seg * 8) * 2;
        CP_ASYNC16(d, wh + so);
    }
}

__global__ __launch_bounds__(256, 1) void gemm_hmma_kernel(const float* __restrict__ bias,
                                                           float* __restrict__ out) {
    extern __shared__ char gsm[];
    const unsigned sbase = smem_u32(gsm);
    const int tid  = threadIdx.x;
    const int lane = tid & 31;
    const int wid  = tid >> 5;
    const int wm   = wid >> 1;          // 0..3 -> 32 m rows each
    const int wn   = wid & 1;           // 0..1 -> 48 n cols each
    const int n0 = blockIdx.x * 96;
    const int m0 = blockIdx.y * 128;

    float acc[2][6][4];
#pragma unroll
    for (int i = 0; i < 2; ++i)
#pragma unroll
        for (int j = 0; j < 6; ++j)
#pragma unroll
            for (int e = 0; e < 4; ++e) acc[i][j][e] = 0.f;

    gemm_issue_stage(sbase, tid, 0, m0, n0);
    CP_COMMIT();
    gemm_issue_stage(sbase + STG_BYTES, tid, GTK, m0, n0);
    CP_COMMIT();
    gemm_issue_stage(sbase + 2 * STG_BYTES, tid, 2 * GTK, m0, n0);
    CP_COMMIT();

    const unsigned aRowSel = (unsigned)(lane & 15) * 128 + ((unsigned)(lane >> 4) << 4);
    const unsigned bRowSel = (unsigned)((lane & 7) | (((lane >> 4) & 1) << 3)) * 128 +
                             (((unsigned)(lane >> 3) & 1) << 4);
    const unsigned aBase = (unsigned)(wm * 32) * 128 + aRowSel;   // + mf*16*128 + ks*32
    const unsigned bBase = (unsigned)(wn * 48) * 128 + bRowSel;   // + g*16*128 + ks*32

    unsigned Af[2][2][4];    // [buf][mf]
    unsigned Bf[2][3][4];    // [buf][g]

    for (int c = 0; c < GITERS; ++c) {
        __syncthreads();                       // all warps done reading stage c-1
        if (c + 3 < GITERS) {
            gemm_issue_stage(sbase + ((c + 3) & 3) * STG_BYTES, tid, (c + 3) * GTK, m0, n0);
        }
        CP_COMMIT();
        CP_WAIT2();                            // stages c AND c+1 now resident

        const unsigned stg = sbase + (c & 3) * STG_BYTES;

        if (c == 0) {                          // cold start: load first frags
#pragma unroll
            for (int mf = 0; mf < 2; ++mf)
                ldsm_x4(stg + swz128(aBase + mf * (16 * 128)), Af[0][mf]);
#pragma unroll
            for (int g = 0; g < 3; ++g)
                ldsm_x4(stg + A_PL + swz128(bBase + g * (16 * 128)), Bf[0][g]);
        }

#pragma unroll
        for (int u = 0; u < 8; ++u) {          // 8 sub-steps of k16
            const int cur = u & 1;
            const int nxt = cur ^ 1;
            if (u < 7) {
                const int un = u + 1;
                const unsigned sub = stg + (un >> 2) * SUB_BYTES;
                const unsigned ko = (unsigned)((un & 3) * 32);
#pragma unroll
                for (int mf = 0; mf < 2; ++mf)
                    ldsm_x4(sub + swz128(aBase + mf * (16 * 128) + ko), Af[nxt][mf]);
#pragma unroll
                for (int g = 0; g < 3; ++g)
                    ldsm_x4(sub + A_PL + swz128(bBase + g * (16 * 128) + ko), Bf[nxt][g]);
            } else if (c + 1 < GITERS) {
                // cross-chunk prefetch: chunk c+1, sub-step 0 (stage c+1 resident)
                const unsigned sub = sbase + ((c + 1) & 3) * STG_BYTES;
#pragma unroll
                for (int mf = 0; mf < 2; ++mf)
                    ldsm_x4(sub + swz128(aBase + mf * (16 * 128)), Af[nxt][mf]);
#pragma unroll
                for (int g = 0; g < 3; ++g)
                    ldsm_x4(sub + A_PL + swz128(bBase + g * (16 * 128)), Bf[nxt][g]);
            }
#pragma unroll
            for (int mf = 0; mf < 2; ++mf)
#pragma unroll
                for (int nf = 0; nf < 6; ++nf)
                    mma_f16(acc[mf][nf], Af[cur][mf], &Bf[cur][nf >> 1][(nf & 1) * 2]);
        }
    }

    // ---- epilogue: bias + relu ----
#pragma unroll
    for (int mf = 0; mf < 2; ++mf) {
        int mlo = m0 + wm * 32 + mf * 16 + (lane >> 2);
#pragma unroll
        for (int nf = 0; nf < 6; ++nf) {
            int n = n0 + wn * 48 + nf * 8 + 2 * (lane & 3);
            if (n < ODIM) {
                float b0 = bias[n], b1 = bias[n + 1];
                float2 v0, v1;
                v0.x = fmaxf(acc[mf][nf][0] + b0, 0.f);
                v0.y = fmaxf(acc[mf][nf][1] + b1, 0.f);
                v1.x = fmaxf(acc[mf][nf][2] + b0, 0.f);
                v1.y = fmaxf(acc[mf][nf][3] + b1, 0.f);
                *reinterpret_cast<float2*>(out + (size_t)mlo * ODIM + n) = v0;
                *reinterpret_cast<float2*>(out + (size_t)(mlo + 8) * ODIM + n) = v1;
            }
        }
    }
}

// ---------------------------------------------------------------------------
extern "C" void kernel_launch(void* const* d_in, const int* in_sizes, int n_in,
                              void* d_out, int out_size) {
    const float* x0  = (const float*)d_in[0];
    const float* x1  = (const float*)d_in[1];
    const float* s1  = (const float*)d_in[2];
    const float* s2  = (const float*)d_in[3];
    const float* Wm  = (const float*)d_in[4];
    const float* bia = (const float*)d_in[5];
    const int*   h1  = (const int*)d_in[6];
    const int*   h2  = (const int*)d_in[7];
    float* out = (float*)d_out;

    // side stream + events for wconv overlap (created on first, uncaptured call)
    static cudaStream_t side = nullptr;
    static cudaEvent_t evFork = nullptr, evJoin = nullptr;
    if (!side) {
        cudaStreamCreateWithFlags(&side, cudaStreamNonBlocking);
        cudaEventCreateWithFlags(&evFork, cudaEventDisableTiming);
        cudaEventCreateWithFlags(&evJoin, cudaEventDisableTiming);
    }

    const int FFT_SMEM = (N_FFT + 128) * (int)sizeof(float2);  // 129 KB
    cudaFuncSetAttribute(fused_fft_kernel, cudaFuncAttributeMaxDynamicSharedMemorySize, FFT_SMEM);
    cudaFuncSetAttribute(gemm_hmma_kernel, cudaFuncAttributeMaxDynamicSharedMemorySize, GEMM_SMEM);

    // fork: wconv on side stream (DRAM-bound; overlaps compute-bound FFT)
    cudaEventRecord(evFork, 0);
    cudaStreamWaitEvent(side, evFork, 0);
    const int wthreads = OPAD * (KDIM / 8);
    wconv_kernel<<<(wthreads + 255) / 256, 256, 0, side>>>(Wm);
    cudaEventRecord(evJoin, side);

    tw_init_kernel<<<(N_FFT + 255) / 256, 256>>>();

    fused_fft_kernel<<<BATCH, 1024, FFT_SMEM>>>(x0, x1, s1, s2, h1, h2);

    // join: gemm needs g_Wh
    cudaStreamWaitEvent(0, evJoin, 0);
    gemm_hmma_kernel<<<dim3((ODIM + 95) / 96, BATCH / 128), 256, GEMM_SMEM>>>(bia, out);
}